// round 2
// baseline (speedup 1.0000x reference)
#include <cuda_runtime.h>
#include <math.h>

// ---------------- problem constants ----------------
#define H_IMG 120
#define W_IMG 160
#define NTOK  19200          // H*W
#define CCH   96
#define NSB   16             // 2 streams * 8 batches, sb = s*8+b
#define KMAX  24             // rope frequencies per axis (c/4)
#define INV_N (1.0f/19200.0f)

// ---------------- scratch: static __device__ (no allocations) ----------------
__device__ float g_q [(size_t)NSB*NTOK*CCH];   // elu(q)+1, NOT roped   [sb][pos][ch]
__device__ float g_kr[(size_t)NSB*NTOK*CCH];   // rope(elu(k)+1)        [sb][pos][ch]
__device__ float g_v [(size_t)NSB*CCH*NTOK];   // v image layout        [sb][ch][pos]
__device__ float g_kv[NSB*3*32*32];            // sum_n k_r[d]*v[e] (unscaled)
__device__ float g_ksum[NSB*CCH];              // sum_n elu(k)+1 (unscaled)
__device__ float g_kvpart[480*3072];           // per-block kv partials (16 sb * 30 blk)
__device__ float g_kspart[4800*CCH];           // per-block ksum partials
__device__ float g_cos[(H_IMG+W_IMG)*KMAX];
__device__ float g_sin[(H_IMG+W_IMG)*KMAX];

typedef unsigned long long ull;

__device__ __forceinline__ ull pk2(float lo, float hi){
    ull r; asm("mov.b64 %0,{%1,%2};" : "=l"(r) : "f"(lo), "f"(hi)); return r;
}
__device__ __forceinline__ void upk2(ull v, float& lo, float& hi){
    asm("mov.b64 {%0,%1},%2;" : "=f"(lo), "=f"(hi) : "l"(v));
}
__device__ __forceinline__ ull f2fma(ull a, ull b, ull c){
    ull d; asm("fma.rn.f32x2 %0,%1,%2,%3;" : "=l"(d) : "l"(a), "l"(b), "l"(c)); return d;
}
__device__ __forceinline__ float elu1(float x){ return x > 0.0f ? x + 1.0f : expf(x); }

// ---------------- kernel: rope cos/sin tables ----------------
__global__ void k_init(){
    int i = blockIdx.x*blockDim.x + threadIdx.x;
    const int total = (H_IMG+W_IMG)*KMAX;
    if (i >= total) return;
    int p = i % KMAX;
    int coord = i / KMAX;
    float pos = (coord < H_IMG) ? (float)coord : (float)(coord - H_IMG);
    float theta = powf(10000.0f, -((float)p)/(float)KMAX);
    float s, c;
    sincosf(pos*theta, &s, &c);
    g_cos[i] = c;
    g_sin[i] = s;
}

// ---------------- kernel: fused GEMM [64 tok x 288] + elu + rope(k) + scatter ----
// smem: Ws[96][288] | Xs[96][64] | part[16][96]
#define SM_GEMM_FLOATS (96*288 + 96*64 + 16*96)

__global__ void __launch_bounds__(256) k_gemm(
    const float* __restrict__ x1, const float* __restrict__ x2,
    const float* __restrict__ Wqk, const float* __restrict__ bqk,
    const float* __restrict__ Wv,  const float* __restrict__ bv)
{
    extern __shared__ float sm[];
    float* Ws   = sm;                  // [k][nn] 96x288
    float* Xs   = sm + 96*288;         // [k][m]  96x64
    float* part = Xs + 96*64;          // [ty][ch] 16x96

    const int tid = threadIdx.x;
    const int bid = blockIdx.x;
    const int sb  = bid / 300;
    const int posbase = (bid % 300) * 64;
    const float* xb = ((sb < 8) ? x1 : x2) + ((size_t)(sb & 7)*NTOK + posbase)*CCH;

    // load W transposed: Ws[k][nn]; nn<192 from Wqk rows, else Wv rows
    for (int idx = tid; idx < 288*24; idx += 256){
        int nn = idx / 24;
        int kk = (idx % 24) * 4;
        const float* src = (nn < 192) ? (Wqk + nn*96 + kk) : (Wv + (nn-192)*96 + kk);
        float4 w = *reinterpret_cast<const float4*>(src);
        Ws[(kk+0)*288+nn] = w.x; Ws[(kk+1)*288+nn] = w.y;
        Ws[(kk+2)*288+nn] = w.z; Ws[(kk+3)*288+nn] = w.w;
    }
    // load X transposed: Xs[k][m]
    for (int idx = tid; idx < 64*24; idx += 256){
        int m  = idx / 24;
        int kk = (idx % 24) * 4;
        float4 v = *reinterpret_cast<const float4*>(xb + (size_t)m*96 + kk);
        Xs[(kk+0)*64+m] = v.x; Xs[(kk+1)*64+m] = v.y;
        Xs[(kk+2)*64+m] = v.z; Xs[(kk+3)*64+m] = v.w;
    }
    __syncthreads();

    const int tx  = tid & 15;          // 16 channel groups of 18
    const int ty  = tid >> 4;          // 16 token groups of 4
    const int nn0 = tx * 18;

    ull acc[4][9];
    #pragma unroll
    for (int m = 0; m < 4; m++)
        #pragma unroll
        for (int t = 0; t < 9; t++) acc[m][t] = 0ull;

    const float* xp = Xs + ty*4;
    #pragma unroll 2
    for (int k = 0; k < 96; k++){
        float4 xa = *reinterpret_cast<const float4*>(xp + k*64);
        const ull* wr = reinterpret_cast<const ull*>(Ws + k*288 + nn0);
        ull w2[9];
        #pragma unroll
        for (int t = 0; t < 9; t++) w2[t] = wr[t];
        ull xd0 = pk2(xa.x, xa.x);
        ull xd1 = pk2(xa.y, xa.y);
        ull xd2 = pk2(xa.z, xa.z);
        ull xd3 = pk2(xa.w, xa.w);
        #pragma unroll
        for (int t = 0; t < 9; t++){
            acc[0][t] = f2fma(xd0, w2[t], acc[0][t]);
            acc[1][t] = f2fma(xd1, w2[t], acc[1][t]);
            acc[2][t] = f2fma(xd2, w2[t], acc[2][t]);
            acc[3][t] = f2fma(xd3, w2[t], acc[3][t]);
        }
    }

    // ---- epilogue ----
    float bias[18];
    #pragma unroll
    for (int cc = 0; cc < 18; cc++){
        int nn = nn0 + cc;
        bias[cc] = (nn < 192) ? bqk[nn] : bv[nn-192];
    }
    float ksl[18];
    #pragma unroll
    for (int cc = 0; cc < 18; cc++) ksl[cc] = 0.0f;

    for (int m = 0; m < 4; m++){
        int pos = posbase + ty*4 + m;
        int ii  = pos / W_IMG;
        int jj  = pos - ii*W_IMG;
        size_t tokbase = ((size_t)sb*NTOK + pos)*CCH;

        float f[18];
        #pragma unroll
        for (int t = 0; t < 9; t++) upk2(acc[m][t], f[2*t], f[2*t+1]);
        #pragma unroll
        for (int cc = 0; cc < 18; cc++){
            int nn = nn0 + cc;
            float val = f[cc] + bias[cc];
            if (nn < 192) val = elu1(val);   // q and k get the elu+1 feature map
            f[cc] = val;
        }
        #pragma unroll
        for (int cc = 0; cc < 18; cc++){
            int nn = nn0 + cc;
            if (nn < 96){
                g_q[tokbase + nn] = f[cc];
            } else if (nn < 192){
                ksl[cc] += f[cc];
            } else {
                g_v[((size_t)sb*CCH + (nn-192))*NTOK + pos] = f[cc];
            }
        }
        // rope + store k pairs (thread ranges start even, so pairs never straddle)
        #pragma unroll
        for (int cc = 0; cc < 18; cc += 2){
            int nn = nn0 + cc;
            if (nn >= 96 && nn < 192){
                int ch = nn - 96;
                int pp = ch >> 1;
                int row = (pp < KMAX) ? ii : (H_IMG + jj);
                int t   = (pp < KMAX) ? pp : (pp - KMAX);
                float c = g_cos[row*KMAX + t];
                float s = g_sin[row*KMAX + t];
                float re = f[cc], im = f[cc+1];
                g_kr[tokbase + ch]     = c*re - s*im;
                g_kr[tokbase + ch + 1] = s*re + c*im;
            }
        }
    }

    // deterministic ksum block partial: part[ty][ch]
    #pragma unroll
    for (int cc = 0; cc < 18; cc++){
        int nn = nn0 + cc;
        if (nn >= 96 && nn < 192) part[ty*96 + (nn-96)] = ksl[cc];
    }
    __syncthreads();
    if (tid < 96){
        float s = 0.0f;
        #pragma unroll
        for (int t = 0; t < 16; t++) s += part[t*96 + tid];
        g_kspart[(size_t)bid*96 + tid] = s;
    }
}

// ---------------- kernel: kv = sum_n k_rope^T * v (block partials) ----------------
// grid (30, 16): block cb handles 5 chunks of 128 tokens for stream-batch sb
#define SM_KV_FLOATS (2*128*100)

__global__ void __launch_bounds__(256) k_kv(){
    extern __shared__ float sm[];
    float* krs = sm;            // [128][100]
    float* vs  = sm + 12800;    // [128][100]
    const int sb  = blockIdx.y;
    const int cb  = blockIdx.x;
    const int tid = threadIdx.x;
    const int d   = tid >> 3;           // 0..31
    const int e0  = (tid & 7) * 4;      // 0,4,...,28

    ull acc[3][2];
    #pragma unroll
    for (int hd = 0; hd < 3; hd++){ acc[hd][0] = 0ull; acc[hd][1] = 0ull; }

    for (int cc = 0; cc < 5; cc++){
        int n0 = (cb*5 + cc) * 128;
        for (int idx = tid; idx < 128*24; idx += 256){
            int nn = idx / 24;
            int kk = (idx % 24) * 4;
            float4 v = *reinterpret_cast<const float4*>(
                g_kr + ((size_t)sb*NTOK + n0 + nn)*CCH + kk);
            float* p = krs + nn*100 + kk;
            p[0] = v.x; p[1] = v.y; p[2] = v.z; p[3] = v.w;
        }
        for (int idx = tid; idx < 96*128; idx += 256){
            int ch = idx >> 7;
            int nn = idx & 127;
            vs[nn*100 + ch] = g_v[((size_t)sb*CCH + ch)*NTOK + n0 + nn];
        }
        __syncthreads();

        #pragma unroll 4
        for (int nn = 0; nn < 128; nn++){
            const float* kr_row = krs + nn*100;
            const float* v_row  = vs  + nn*100;
            #pragma unroll
            for (int hd = 0; hd < 3; hd++){
                float kr = kr_row[32*hd + d];
                ull kr2 = pk2(kr, kr);
                const ull* vp = reinterpret_cast<const ull*>(v_row + 32*hd + e0);
                acc[hd][0] = f2fma(kr2, vp[0], acc[hd][0]);
                acc[hd][1] = f2fma(kr2, vp[1], acc[hd][1]);
            }
        }
        __syncthreads();
    }

    #pragma unroll
    for (int hd = 0; hd < 3; hd++){
        float a, b, c, e;
        upk2(acc[hd][0], a, b);
        upk2(acc[hd][1], c, e);
        float* dst = g_kvpart + ((size_t)(sb*30 + cb))*3072 + (hd*32 + d)*32 + e0;
        dst[0] = a; dst[1] = b; dst[2] = c; dst[3] = e;
    }
}

// ---------------- kernel: deterministic reduction of partials ----------------
__global__ void k_red(){
    int idx = blockIdx.x*blockDim.x + threadIdx.x;
    if (idx < NSB*CCH){
        int sb = idx / 96, ch = idx % 96;
        float s = 0.0f;
        for (int b = 0; b < 300; b++) s += g_kspart[((size_t)sb*300 + b)*96 + ch];
        g_ksum[idx] = s;
    }
    if (idx < NSB*3072){
        int sb = idx / 3072, r = idx % 3072;
        float s = 0.0f;
        for (int b = 0; b < 30; b++) s += g_kvpart[((size_t)sb*30 + b)*3072 + r];
        g_kv[idx] = s;
    }
}

// ---------------- kernel: output = rope(q)·kv·z + depthwise conv ----------------
// grid (120, 16), 160 threads (one per column j); block = one image row of one sb
#define SM_OUT_FLOATS (160*100 + 3072 + 96 + 864 + 96 + 24 + 24)

__device__ __forceinline__ float convpix(int ch, int sb, int i, int j,
                                         const float* ws, const float* wb){
    const float* vch = g_v + ((size_t)sb*CCH + ch)*NTOK;
    const float* wk  = ws + ch*9;
    float s = wb[ch];
    #pragma unroll
    for (int di = -1; di <= 1; di++){
        int ii = i + di;
        if (ii < 0 || ii >= H_IMG) continue;
        const float* vr = vch + ii*W_IMG;
        #pragma unroll
        for (int dj = -1; dj <= 1; dj++){
            int jj = j + dj;
            if (jj < 0 || jj >= W_IMG) continue;
            s += wk[(di+1)*3 + (dj+1)] * vr[jj];
        }
    }
    return s;
}

__global__ void __launch_bounds__(160) k_out(
    const float* __restrict__ lepe_w, const float* __restrict__ lepe_b,
    float* __restrict__ out)
{
    extern __shared__ float sm[];
    float* qs  = sm;             // [160][100]
    float* kvs = sm + 16000;     // [3][32][32]
    float* kms = kvs + 3072;     // [96]
    float* ws  = kms + 96;       // [96][9]
    float* wb  = ws + 864;       // [96]
    float* ci  = wb + 96;        // [24]
    float* si  = ci + 24;        // [24]

    const int i   = blockIdx.x;
    const int sb  = blockIdx.y;
    const int other = sb ^ 8;    // same batch, other stream
    const int tid = threadIdx.x;
    const int j   = tid;

    {
        const float* qsrc = g_q + ((size_t)sb*NTOK + (size_t)i*W_IMG)*CCH;
        for (int idx = tid; idx < 3840; idx += 160){
            float4 v = *reinterpret_cast<const float4*>(qsrc + idx*4);
            int tt = idx / 24;
            int ch = (idx % 24) * 4;
            float* p = qs + tt*100 + ch;
            p[0] = v.x; p[1] = v.y; p[2] = v.z; p[3] = v.w;
        }
        for (int idx = tid; idx < 3072; idx += 160) kvs[idx] = g_kv[other*3072 + idx];
        for (int idx = tid; idx < 96;   idx += 160) kms[idx] = g_ksum[other*96 + idx] * INV_N;
        for (int idx = tid; idx < 864;  idx += 160) ws[idx]  = lepe_w[idx];
        for (int idx = tid; idx < 96;   idx += 160) wb[idx]  = lepe_b[idx];
        for (int idx = tid; idx < 24;   idx += 160){
            ci[idx] = g_cos[i*KMAX + idx];
            si[idx] = g_sin[i*KMAX + idx];
        }
    }
    __syncthreads();

    const float* q = qs + j*100;
    const int rowj = H_IMG + j;
    const size_t outbase = ((size_t)sb*CCH)*NTOK + (size_t)i*W_IMG + j;

    #pragma unroll
    for (int hd = 0; hd < 3; hd++){
        const int base = 32*hd;

        // z = 1/(q_raw · kmean_other + 1e-6)
        float zacc = 0.0f;
        #pragma unroll
        for (int dd = 0; dd < 32; dd++) zacc += q[base+dd]*kms[base+dd];
        float zi = INV_N / (zacc + 1e-6f);

        // rope(q) for this head's 16 pairs
        float qr[32];
        #pragma unroll
        for (int t = 0; t < 16; t++){
            int pp = 16*hd + t;
            float c, s;
            if (pp < KMAX){ c = ci[pp]; s = si[pp]; }
            else { c = g_cos[rowj*KMAX + pp - KMAX]; s = g_sin[rowj*KMAX + pp - KMAX]; }
            float re = q[base + 2*t], im = q[base + 2*t + 1];
            qr[2*t]   = c*re - s*im;
            qr[2*t+1] = s*re + c*im;
        }

        // o[e] = sum_d qr[d] * kv_other[hd][d][e]
        ull acc2[16];
        #pragma unroll
        for (int t = 0; t < 16; t++) acc2[t] = 0ull;
        const float* kvh = kvs + hd*1024;
        #pragma unroll 4
        for (int dd = 0; dd < 32; dd++){
            ull qd = pk2(qr[dd], qr[dd]);
            const ull* kp = reinterpret_cast<const ull*>(kvh + dd*32);
            #pragma unroll
            for (int t = 0; t < 16; t++) acc2[t] = f2fma(qd, kp[t], acc2[t]);
        }

        #pragma unroll
        for (int t = 0; t < 16; t++){
            float o0, o1;
            upk2(acc2[t], o0, o1);
            int ch0 = base + 2*t;
            float r0 = o0*zi + convpix(ch0,   sb, i, j, ws, wb);
            float r1 = o1*zi + convpix(ch0+1, sb, i, j, ws, wb);
            out[outbase + (size_t)ch0*NTOK]     = r0;
            out[outbase + (size_t)(ch0+1)*NTOK] = r1;
        }
    }
}

// ---------------- launch ----------------
extern "C" void kernel_launch(void* const* d_in, const int* in_sizes, int n_in,
                              void* d_out, int out_size)
{
    (void)in_sizes; (void)n_in; (void)out_size;
    const float* x1     = (const float*)d_in[0];
    const float* x2     = (const float*)d_in[1];
    const float* Wqk    = (const float*)d_in[2];
    const float* bqk    = (const float*)d_in[3];
    const float* Wv     = (const float*)d_in[4];
    const float* bv     = (const float*)d_in[5];
    const float* lepe_w = (const float*)d_in[6];
    const float* lepe_b = (const float*)d_in[7];
    float* out = (float*)d_out;

    cudaFuncSetAttribute(k_gemm, cudaFuncAttributeMaxDynamicSharedMemorySize,
                         SM_GEMM_FLOATS*4);
    cudaFuncSetAttribute(k_kv, cudaFuncAttributeMaxDynamicSharedMemorySize,
                         SM_KV_FLOATS*4);
    cudaFuncSetAttribute(k_out, cudaFuncAttributeMaxDynamicSharedMemorySize,
                         SM_OUT_FLOATS*4);

    k_init<<<27, 256>>>();
    k_gemm<<<4800, 256, SM_GEMM_FLOATS*4>>>(x1, x2, Wqk, bqk, Wv, bv);
    dim3 gkv(30, 16);
    k_kv<<<gkv, 256, SM_KV_FLOATS*4>>>();
    k_red<<<192, 256>>>();
    dim3 go(120, 16);
    k_out<<<go, 160, SM_OUT_FLOATS*4>>>(lepe_w, lepe_b, out);
}

// round 3
// speedup vs baseline: 1.1823x; 1.1823x over previous
#include <cuda_runtime.h>
#include <math.h>

// ---------------- problem constants ----------------
#define H_IMG 120
#define W_IMG 160
#define NTOK  19200          // H*W
#define CCH   96
#define NSB   16             // 2 streams * 8 batches, sb = s*8+b
#define KMAX  24             // rope frequencies per axis (c/4)
#define INV_N (1.0f/19200.0f)

// ---------------- scratch: static __device__ (no allocations) ----------------
__device__ float g_q [(size_t)NSB*NTOK*CCH];   // elu(q)+1, NOT roped   [sb][pos][ch]
__device__ float g_kr[(size_t)NSB*NTOK*CCH];   // rope(elu(k)+1)        [sb][pos][ch]
__device__ float g_v [(size_t)NSB*CCH*NTOK];   // v image layout        [sb][ch][pos]
__device__ float g_kv[NSB*3072];               // sum_n k_r[d]*v[e] (unscaled)
__device__ float g_ksum[NSB*CCH];              // sum_n elu(k)+1 (unscaled)
__device__ float g_kvpart[480*3072];           // per-block kv partials
__device__ float g_kspart[4800*CCH];           // per-block ksum partials
__device__ float g_cos[(H_IMG+W_IMG)*KMAX];
__device__ float g_sin[(H_IMG+W_IMG)*KMAX];

typedef unsigned long long ull;

__device__ __forceinline__ ull pk2(float lo, float hi){
    ull r; asm("mov.b64 %0,{%1,%2};" : "=l"(r) : "f"(lo), "f"(hi)); return r;
}
__device__ __forceinline__ void upk2(ull v, float& lo, float& hi){
    asm("mov.b64 {%0,%1},%2;" : "=f"(lo), "=f"(hi) : "l"(v));
}
__device__ __forceinline__ ull f2fma(ull a, ull b, ull c){
    ull d; asm("fma.rn.f32x2 %0,%1,%2,%3;" : "=l"(d) : "l"(a), "l"(b), "l"(c)); return d;
}
__device__ __forceinline__ float elu1(float x){ return x > 0.0f ? x + 1.0f : expf(x); }

// ---------------- kernel: rope cos/sin tables ----------------
__global__ void k_init(){
    int i = blockIdx.x*blockDim.x + threadIdx.x;
    const int total = (H_IMG+W_IMG)*KMAX;
    if (i >= total) return;
    int p = i % KMAX;
    int coord = i / KMAX;
    float pos = (coord < H_IMG) ? (float)coord : (float)(coord - H_IMG);
    float theta = powf(10000.0f, -((float)p)/(float)KMAX);
    float s, c;
    sincosf(pos*theta, &s, &c);
    g_cos[i] = c;
    g_sin[i] = s;
}

// ---------------- kernel: fused GEMM [64 tok x 288] + elu + rope(k) ----------
// phase1 smem: Ws[96][288] | Xs[96][64]
// phase2 smem (aliased): Os[64][196] | Vs2[64][97] | part[16][96]
#define SM_GEMM_FLOATS (96*288 + 96*64)

__global__ void __launch_bounds__(256) k_gemm(
    const float* __restrict__ x1, const float* __restrict__ x2,
    const float* __restrict__ Wqk, const float* __restrict__ bqk,
    const float* __restrict__ Wv,  const float* __restrict__ bv)
{
    extern __shared__ float sm[];
    float* Ws   = sm;                       // [k][nn] 96x288
    float* Xs   = sm + 96*288;              // [k][m]  96x64
    float* Os   = sm;                       // [64][196] (phase 2)
    float* Vs2  = sm + 64*196;              // [64][97]  (phase 2)
    float* part = sm + 64*196 + 64*97;      // [16][96]  (phase 2)

    const int tid = threadIdx.x;
    const int bid = blockIdx.x;
    const int sb  = bid / 300;
    const int posbase = (bid % 300) * 64;
    const float* xb = ((sb < 8) ? x1 : x2) + ((size_t)(sb & 7)*NTOK + posbase)*CCH;

    // load W transposed: Ws[k][nn]
    for (int idx = tid; idx < 288*24; idx += 256){
        int nn = idx / 24;
        int kk = (idx % 24) * 4;
        const float* src = (nn < 192) ? (Wqk + nn*96 + kk) : (Wv + (nn-192)*96 + kk);
        float4 w = *reinterpret_cast<const float4*>(src);
        Ws[(kk+0)*288+nn] = w.x; Ws[(kk+1)*288+nn] = w.y;
        Ws[(kk+2)*288+nn] = w.z; Ws[(kk+3)*288+nn] = w.w;
    }
    // load X transposed: Xs[k][m]
    for (int idx = tid; idx < 64*24; idx += 256){
        int m  = idx / 24;
        int kk = (idx % 24) * 4;
        float4 v = *reinterpret_cast<const float4*>(xb + (size_t)m*96 + kk);
        Xs[(kk+0)*64+m] = v.x; Xs[(kk+1)*64+m] = v.y;
        Xs[(kk+2)*64+m] = v.z; Xs[(kk+3)*64+m] = v.w;
    }
    __syncthreads();

    const int tx  = tid & 15;          // 16 channel groups of 18
    const int ty  = tid >> 4;          // 16 token groups of 4
    const int nn0 = tx * 18;

    ull acc[4][9];
    #pragma unroll
    for (int m = 0; m < 4; m++)
        #pragma unroll
        for (int t = 0; t < 9; t++) acc[m][t] = 0ull;

    const float* xp = Xs + ty*4;
    const float* wp = Ws + nn0;

    // software-pipelined main loop (register double buffer)
    ull w2[9]; float4 xa;
    {
        const ull* wr = reinterpret_cast<const ull*>(wp);
        #pragma unroll
        for (int t = 0; t < 9; t++) w2[t] = wr[t];
        xa = *reinterpret_cast<const float4*>(xp);
    }
    #pragma unroll 2
    for (int k = 0; k < 96; k++){
        ull w2n[9]; float4 xan;
        if (k < 95){
            const ull* wr = reinterpret_cast<const ull*>(wp + (k+1)*288);
            #pragma unroll
            for (int t = 0; t < 9; t++) w2n[t] = wr[t];
            xan = *reinterpret_cast<const float4*>(xp + (k+1)*64);
        }
        ull xd0 = pk2(xa.x, xa.x);
        ull xd1 = pk2(xa.y, xa.y);
        ull xd2 = pk2(xa.z, xa.z);
        ull xd3 = pk2(xa.w, xa.w);
        #pragma unroll
        for (int t = 0; t < 9; t++){
            acc[0][t] = f2fma(xd0, w2[t], acc[0][t]);
            acc[1][t] = f2fma(xd1, w2[t], acc[1][t]);
            acc[2][t] = f2fma(xd2, w2[t], acc[2][t]);
            acc[3][t] = f2fma(xd3, w2[t], acc[3][t]);
        }
        if (k < 95){
            #pragma unroll
            for (int t = 0; t < 9; t++) w2[t] = w2n[t];
            xa = xan;
        }
    }
    __syncthreads();                   // Ws/Xs dead; smem now Os/Vs2/part

    // ---- epilogue: bias + elu + rope(k) -> stage to smem ----
    float bias[18];
    #pragma unroll
    for (int cc = 0; cc < 18; cc++){
        int nn = nn0 + cc;
        bias[cc] = (nn < 192) ? bqk[nn] : bv[nn-192];
    }
    float ksl[18];
    #pragma unroll
    for (int cc = 0; cc < 18; cc++) ksl[cc] = 0.0f;

    for (int m = 0; m < 4; m++){
        int tokl = ty*4 + m;
        int pos  = posbase + tokl;
        int ii   = pos / W_IMG;
        int jj   = pos - ii*W_IMG;

        float f[18];
        #pragma unroll
        for (int t = 0; t < 9; t++) upk2(acc[m][t], f[2*t], f[2*t+1]);
        #pragma unroll
        for (int cc = 0; cc < 18; cc++){
            int nn = nn0 + cc;
            float val = f[cc] + bias[cc];
            if (nn < 192) val = elu1(val);
            f[cc] = val;
        }
        // q channels + ksum accumulation + v channels
        #pragma unroll
        for (int cc = 0; cc < 18; cc++){
            int nn = nn0 + cc;
            if (nn < 96){
                Os[tokl*196 + nn] = f[cc];
            } else if (nn < 192){
                ksl[cc] += f[cc];
            } else {
                Vs2[tokl*97 + (nn-192)] = f[cc];
            }
        }
        // rope + stage k pairs (nn0 even -> pairs intact)
        #pragma unroll
        for (int cc = 0; cc < 18; cc += 2){
            int nn = nn0 + cc;
            if (nn >= 96 && nn < 192){
                int ch = nn - 96;
                int pp = ch >> 1;
                int row = (pp < KMAX) ? ii : (H_IMG + jj);
                int t   = (pp < KMAX) ? pp : (pp - KMAX);
                float c = g_cos[row*KMAX + t];
                float s = g_sin[row*KMAX + t];
                float re = f[cc], im = f[cc+1];
                Os[tokl*196 + nn]     = c*re - s*im;
                Os[tokl*196 + nn + 1] = s*re + c*im;
            }
        }
    }
    // ksum block partials
    #pragma unroll
    for (int cc = 0; cc < 18; cc++){
        int nn = nn0 + cc;
        if (nn >= 96 && nn < 192) part[ty*96 + (nn-96)] = ksl[cc];
    }
    __syncthreads();

    // ---- coalesced writeout ----
    size_t qbase = ((size_t)sb*NTOK + posbase)*CCH;
    for (int idx = tid; idx < 1536; idx += 256){
        int tok = idx / 24;
        int c4  = (idx % 24) * 4;
        float4 vq = *reinterpret_cast<const float4*>(Os + tok*196 + c4);
        *reinterpret_cast<float4*>(g_q + qbase + (size_t)tok*96 + c4) = vq;
        float4 vk = *reinterpret_cast<const float4*>(Os + tok*196 + 96 + c4);
        *reinterpret_cast<float4*>(g_kr + qbase + (size_t)tok*96 + c4) = vk;
    }
    for (int idx = tid; idx < 1536; idx += 256){
        int t4 = idx & 15;
        int ch = idx >> 4;
        float4 v;
        v.x = Vs2[(t4*4+0)*97 + ch];
        v.y = Vs2[(t4*4+1)*97 + ch];
        v.z = Vs2[(t4*4+2)*97 + ch];
        v.w = Vs2[(t4*4+3)*97 + ch];
        *reinterpret_cast<float4*>(
            g_v + ((size_t)sb*CCH + ch)*NTOK + posbase + t4*4) = v;
    }
    if (tid < 96){
        float s = 0.0f;
        #pragma unroll
        for (int t = 0; t < 16; t++) s += part[t*96 + tid];
        g_kspart[(size_t)bid*96 + tid] = s;
    }
}

// ---------------- kernel: kv = sum_n k_rope^T * v (block partials) ----------------
#define VS_STRIDE 102
#define SM_KV_FLOATS (128*100 + 128*VS_STRIDE)

__global__ void __launch_bounds__(256) k_kv(){
    extern __shared__ float sm[];
    float* krs = sm;                 // [128][100]
    float* vs  = sm + 128*100;       // [128][102]
    const int sb  = blockIdx.y;
    const int cb  = blockIdx.x;
    const int tid = threadIdx.x;
    const int d   = tid >> 3;           // 0..31
    const int e0  = (tid & 7) * 4;      // 0,4,...,28

    ull acc[3][2];
    #pragma unroll
    for (int hd = 0; hd < 3; hd++){ acc[hd][0] = 0ull; acc[hd][1] = 0ull; }

    for (int cc = 0; cc < 5; cc++){
        int n0 = (cb*5 + cc) * 128;
        for (int idx = tid; idx < 128*24; idx += 256){
            int nn = idx / 24;
            int kk = (idx % 24) * 4;
            float4 v = *reinterpret_cast<const float4*>(
                g_kr + ((size_t)sb*NTOK + n0 + nn)*CCH + kk);
            *reinterpret_cast<float4*>(krs + nn*100 + kk) = v;
        }
        for (int idx = tid; idx < 96*128; idx += 256){
            int ch = idx >> 7;
            int nn = idx & 127;
            vs[nn*VS_STRIDE + ch] = g_v[((size_t)sb*CCH + ch)*NTOK + n0 + nn];
        }
        __syncthreads();

        #pragma unroll 4
        for (int nn = 0; nn < 128; nn++){
            const float* kr_row = krs + nn*100;
            const float* v_row  = vs  + nn*VS_STRIDE;
            #pragma unroll
            for (int hd = 0; hd < 3; hd++){
                float kr = kr_row[32*hd + d];
                ull kr2 = pk2(kr, kr);
                const ull* vp = reinterpret_cast<const ull*>(v_row + 32*hd + e0);
                acc[hd][0] = f2fma(kr2, vp[0], acc[hd][0]);
                acc[hd][1] = f2fma(kr2, vp[1], acc[hd][1]);
            }
        }
        __syncthreads();
    }

    #pragma unroll
    for (int hd = 0; hd < 3; hd++){
        float a, b, c, e;
        upk2(acc[hd][0], a, b);
        upk2(acc[hd][1], c, e);
        float* dst = g_kvpart + ((size_t)(sb*30 + cb))*3072 + (hd*32 + d)*32 + e0;
        dst[0] = a; dst[1] = b; dst[2] = c; dst[3] = e;
    }
}

// ---------------- kernel: deterministic reduction of partials ----------------
__global__ void k_red(){
    int idx = blockIdx.x*blockDim.x + threadIdx.x;
    if (idx < NSB*CCH){
        int sb = idx / 96, ch = idx % 96;
        float s = 0.0f;
        for (int b = 0; b < 300; b++) s += g_kspart[((size_t)sb*300 + b)*96 + ch];
        g_ksum[idx] = s;
    }
    if (idx < NSB*3072){
        int sb = idx / 3072, r = idx % 3072;
        float s = 0.0f;
        for (int b = 0; b < 30; b++) s += g_kvpart[((size_t)sb*30 + b)*3072 + r];
        g_kv[idx] = s;
    }
}

// ---------------- kernel: output = rope(q)·kv·z + depthwise conv ----------------
// grid (120, 16), 160 threads; conv staged per-head in smem, zero-padded.
#define VROW 162
#define SM_OUT_FLOATS (3*32*VROW + 3072 + 96 + 864 + 96 + 24 + 24)

__global__ void __launch_bounds__(160) k_out(
    const float* __restrict__ lepe_w, const float* __restrict__ lepe_b,
    float* __restrict__ out)
{
    extern __shared__ float sm[];
    float* vs3 = sm;               // [3 rows][32 ch][VROW], col 0 & 161 pad
    float* kvs = sm + 3*32*VROW;   // [3][32][32]
    float* kms = kvs + 3072;       // [96]
    float* ws  = kms + 96;         // [96][9]
    float* wb  = ws + 864;         // [96]
    float* ci  = wb + 96;          // [24] row-angle cos
    float* si  = ci + 24;          // [24] row-angle sin

    const int i   = blockIdx.x;
    const int sb  = blockIdx.y;
    const int other = sb ^ 8;      // same batch, other stream
    const int tid = threadIdx.x;
    const int j   = tid;

    for (int idx = tid; idx < 3072; idx += 160) kvs[idx] = g_kv[other*3072 + idx];
    for (int idx = tid; idx < 96;   idx += 160) kms[idx] = g_ksum[other*96 + idx] * INV_N;
    for (int idx = tid; idx < 864;  idx += 160) ws[idx]  = lepe_w[idx];
    for (int idx = tid; idx < 96;   idx += 160) wb[idx]  = lepe_b[idx];
    for (int idx = tid; idx < 24;   idx += 160){
        ci[idx] = g_cos[i*KMAX + idx];
        si[idx] = g_sin[i*KMAX + idx];
    }

    const size_t qrowbase = ((size_t)sb*NTOK + (size_t)i*W_IMG + j)*CCH;
    const int coltab = (H_IMG + j)*KMAX;
    const size_t outbase = ((size_t)sb*CCH)*NTOK + (size_t)i*W_IMG + j;

    for (int hd = 0; hd < 3; hd++){
        __syncthreads();          // protect vs3 from previous iteration readers
        // ---- stage v rows for this head's 32 channels, zero-padded ----
        // pad columns
        for (int idx = tid; idx < 3*32*2; idx += 160){
            int rc = idx >> 1;
            vs3[rc*VROW + ((idx & 1) ? (VROW-1) : 0)] = 0.0f;
        }
        // rows (float4 loads, scalar stores due to +1 column offset)
        for (int idx = tid; idx < 3*32*40; idx += 160){
            int rr  = idx / 1280;          // 0..2 -> image row i-1+rr
            int rem = idx - rr*1280;
            int ch  = rem / 40;            // 0..31 within head
            int q4  = rem - ch*40;         // 0..39 -> cols 4q..4q+3
            int iimg = i - 1 + rr;
            float4 v;
            if (iimg >= 0 && iimg < H_IMG){
                v = *reinterpret_cast<const float4*>(
                    g_v + ((size_t)sb*CCH + (32*hd + ch))*NTOK
                        + (size_t)iimg*W_IMG + q4*4);
            } else {
                v.x = v.y = v.z = v.w = 0.0f;
            }
            float* dst = vs3 + (rr*32 + ch)*VROW + 1 + q4*4;
            dst[0] = v.x; dst[1] = v.y; dst[2] = v.z; dst[3] = v.w;
        }
        __syncthreads();

        // ---- per-pixel compute ----
        const int base = 32*hd;

        // load raw q for this head: one aligned 128B line
        float qreg[32];
        #pragma unroll
        for (int t = 0; t < 8; t++){
            float4 v = *reinterpret_cast<const float4*>(g_q + qrowbase + base + t*4);
            qreg[4*t] = v.x; qreg[4*t+1] = v.y; qreg[4*t+2] = v.z; qreg[4*t+3] = v.w;
        }

        // z = INV_N / (q_raw . kmean_other + 1e-6)
        float zacc = 0.0f;
        #pragma unroll
        for (int dd = 0; dd < 32; dd++) zacc += qreg[dd]*kms[base+dd];
        float zi = INV_N / (zacc + 1e-6f);

        // rope(q): head pairs 16hd .. 16hd+15
        float qr[32];
        #pragma unroll
        for (int t = 0; t < 16; t++){
            int pp = 16*hd + t;
            float c, s;
            if (pp < KMAX){ c = ci[pp]; s = si[pp]; }
            else { c = g_cos[coltab + pp - KMAX]; s = g_sin[coltab + pp - KMAX]; }
            float re = qreg[2*t], im = qreg[2*t+1];
            qr[2*t]   = c*re - s*im;
            qr[2*t+1] = s*re + c*im;
        }

        // o[e] = sum_d qr[d] * kv_other[hd][d][e]
        ull acc2[16];
        #pragma unroll
        for (int t = 0; t < 16; t++) acc2[t] = 0ull;
        const float* kvh = kvs + hd*1024;
        #pragma unroll 4
        for (int dd = 0; dd < 32; dd++){
            ull qd = pk2(qr[dd], qr[dd]);
            const ull* kp = reinterpret_cast<const ull*>(kvh + dd*32);
            #pragma unroll
            for (int t = 0; t < 16; t++) acc2[t] = f2fma(qd, kp[t], acc2[t]);
        }

        // conv (branchless, zero-padded smem) + store
        #pragma unroll
        for (int t = 0; t < 16; t++){
            float o0, o1;
            upk2(acc2[t], o0, o1);
            int chl0 = 2*t;                 // within head
            int ch0  = base + chl0;         // global channel
            float s0 = wb[ch0], s1 = wb[ch0+1];
            const float* wk0 = ws + ch0*9;
            const float* wk1 = wk0 + 9;
            #pragma unroll
            for (int rr = 0; rr < 3; rr++){
                const float* r0 = vs3 + (rr*32 + chl0)*VROW + 1 + j;
                const float* r1 = r0 + VROW;
                s0 += wk0[rr*3+0]*r0[-1] + wk0[rr*3+1]*r0[0] + wk0[rr*3+2]*r0[1];
                s1 += wk1[rr*3+0]*r1[-1] + wk1[rr*3+1]*r1[0] + wk1[rr*3+2]*r1[1];
            }
            out[outbase + (size_t)ch0*NTOK]     = o0*zi + s0;
            out[outbase + (size_t)(ch0+1)*NTOK] = o1*zi + s1;
        }
    }
}

// ---------------- launch ----------------
extern "C" void kernel_launch(void* const* d_in, const int* in_sizes, int n_in,
                              void* d_out, int out_size)
{
    (void)in_sizes; (void)n_in; (void)out_size;
    const float* x1     = (const float*)d_in[0];
    const float* x2     = (const float*)d_in[1];
    const float* Wqk    = (const float*)d_in[2];
    const float* bqk    = (const float*)d_in[3];
    const float* Wv     = (const float*)d_in[4];
    const float* bv     = (const float*)d_in[5];
    const float* lepe_w = (const float*)d_in[6];
    const float* lepe_b = (const float*)d_in[7];
    float* out = (float*)d_out;

    cudaFuncSetAttribute(k_gemm, cudaFuncAttributeMaxDynamicSharedMemorySize,
                         SM_GEMM_FLOATS*4);
    cudaFuncSetAttribute(k_kv, cudaFuncAttributeMaxDynamicSharedMemorySize,
                         SM_KV_FLOATS*4);
    cudaFuncSetAttribute(k_out, cudaFuncAttributeMaxDynamicSharedMemorySize,
                         SM_OUT_FLOATS*4);

    k_init<<<27, 256>>>();
    k_gemm<<<4800, 256, SM_GEMM_FLOATS*4>>>(x1, x2, Wqk, bqk, Wv, bv);
    dim3 gkv(30, 16);
    k_kv<<<gkv, 256, SM_KV_FLOATS*4>>>();
    k_red<<<192, 256>>>();
    dim3 go(120, 16);
    k_out<<<go, 160, SM_OUT_FLOATS*4>>>(lepe_w, lepe_b, out);
}